// round 7
// baseline (speedup 1.0000x reference)
#include <cuda_runtime.h>
#include <cstdint>

#define NTOK 1024
#define NHEAD 20003
#define HCHUNKS 626          // head row chunks of 32 (20032 rows padded)
#define NCH1 625             // tail1: 20000 / 32
#define NCH2 2500            // tail2: 160000 / 64
#define NCH3 2117            // tail3: ceil(67735/32), padded to 67744
#define V3PAD (NCH3 * 32)
#define TILES1 2
#define TILES2 11
#define TILES3 6

// ---------------- scratch (device globals; no allocs) ----------------
__device__ __align__(256) float g_headW[20032 * 512];   // W0 ++ CW ++ zero pad
__device__ __align__(256) float g_headB[20032];
__device__ __align__(256) float g_W3p[V3PAD * 8];
__device__ __align__(256) float g_b3p[V3PAD];
__device__ __align__(256) float g_hp0[NTOK * 512];
__device__ __align__(256) float g_hp1[NTOK * 128];
__device__ __align__(256) float g_hp2[NTOK * 32];
__device__ __align__(256) float g_hp3[NTOK * 8];
__device__ float g_ph[NTOK * HCHUNKS];
__device__ float g_nh[NTOK];
__device__ float g_nt[NTOK];
__device__ float g_pt1[TILES1 * 64 * NCH1];
__device__ float g_pt2[TILES2 * 64 * NCH2];
__device__ float g_pt3[TILES3 * 64 * NCH3];
__device__ int   g_pos[NTOK];
__device__ int   g_list[3][NTOK];
__device__ int   g_cnt[3];

// ---------------- f32x2 helpers ----------------
__device__ __forceinline__ unsigned long long ffma2(unsigned long long a,
                                                    unsigned long long b,
                                                    unsigned long long c) {
    unsigned long long d;
    asm("fma.rn.f32x2 %0, %1, %2, %3;" : "=l"(d) : "l"(a), "l"(b), "l"(c));
    return d;
}
__device__ __forceinline__ float f2lo(unsigned long long v) { return __uint_as_float((unsigned)v); }
__device__ __forceinline__ float f2hi(unsigned long long v) { return __uint_as_float((unsigned)(v >> 32)); }

// ---------------- 0) prep: pack head weights, pad W3 ----------------
__global__ void k_prep(const float4* __restrict__ W0, const float* __restrict__ b0,
                       const float4* __restrict__ CW, const float* __restrict__ CB,
                       const float4* __restrict__ W3, const float* __restrict__ b3) {
    int i = blockIdx.x * 256 + threadIdx.x;
    int stride = gridDim.x * 256;
    float4 z = make_float4(0.f, 0.f, 0.f, 0.f);
    float4* HW = (float4*)g_headW;
    for (int idx = i; idx < 20032 * 128; idx += stride) {
        float4 v = z;
        if (idx < 20000 * 128) v = W0[idx];
        else if (idx < NHEAD * 128) v = CW[idx - 20000 * 128];
        HW[idx] = v;
    }
    float4* W3P = (float4*)g_W3p;
    for (int idx = i; idx < V3PAD * 2; idx += stride)
        W3P[idx] = (idx < 67735 * 2) ? W3[idx] : z;
    for (int idx = i; idx < 20032; idx += stride)
        g_headB[idx] = (idx < 20000) ? b0[idx] : (idx < NHEAD ? CB[idx - 20000] : 0.f);
    for (int idx = i; idx < V3PAD; idx += stride)
        g_b3p[idx] = (idx < 67735) ? b3[idx] : 0.f;
}

// ---------------- 1) projections (8-token tiles) ----------------
__global__ void __launch_bounds__(512)
k_proj(const float* __restrict__ hidden,
       const float* __restrict__ p0, const float* __restrict__ p1,
       const float* __restrict__ p2, const float* __restrict__ p3) {
    __shared__ float h[8][512];
    int t0 = blockIdx.x * 8;
    int tid = threadIdx.x;
    for (int i = tid; i < 8 * 512; i += 512)
        h[i >> 9][i & 511] = hidden[(t0 + (i >> 9)) * 512 + (i & 511)];
    __syncthreads();
    {
        int j = tid;
        float a[8];
#pragma unroll
        for (int i = 0; i < 8; i++) a[i] = 0.f;
#pragma unroll 4
        for (int k = 0; k < 512; k++) {
            float w = p0[k * 512 + j];
#pragma unroll
            for (int i = 0; i < 8; i++) a[i] = fmaf(h[i][k], w, a[i]);
        }
#pragma unroll
        for (int i = 0; i < 8; i++) g_hp0[(t0 + i) * 512 + j] = a[i];
    }
    if (tid < 128) {
        int j = tid;
        float a[8];
#pragma unroll
        for (int i = 0; i < 8; i++) a[i] = 0.f;
#pragma unroll 4
        for (int k = 0; k < 512; k++) {
            float w = p1[k * 128 + j];
#pragma unroll
            for (int i = 0; i < 8; i++) a[i] = fmaf(h[i][k], w, a[i]);
        }
#pragma unroll
        for (int i = 0; i < 8; i++) g_hp1[(t0 + i) * 128 + j] = a[i];
    }
    if (tid < 32) {
        int j = tid;
        float a[8];
#pragma unroll
        for (int i = 0; i < 8; i++) a[i] = 0.f;
#pragma unroll 4
        for (int k = 0; k < 512; k++) {
            float w = p2[k * 32 + j];
#pragma unroll
            for (int i = 0; i < 8; i++) a[i] = fmaf(h[i][k], w, a[i]);
        }
#pragma unroll
        for (int i = 0; i < 8; i++) g_hp2[(t0 + i) * 32 + j] = a[i];
    }
    if (tid < 8) {
        int j = tid;
        float a[8];
#pragma unroll
        for (int i = 0; i < 8; i++) a[i] = 0.f;
#pragma unroll 4
        for (int k = 0; k < 512; k++) {
            float w = p3[k * 8 + j];
#pragma unroll
            for (int i = 0; i < 8; i++) a[i] = fmaf(h[i][k], w, a[i]);
        }
#pragma unroll
        for (int i = 0; i < 8; i++) g_hp3[(t0 + i) * 8 + j] = a[i];
    }
}

// ---------------- 2) cluster-id + compaction ----------------
__global__ void k_compact(const int* __restrict__ target) {
    int t = threadIdx.x;
    if (t < 3) g_cnt[t] = 0;
    __syncthreads();
    int tg = target[t];
    int cid = (tg >= 20000) + (tg >= 40000) + (tg >= 200000);
    if (cid > 0) {
        int p = atomicAdd(&g_cnt[cid - 1], 1);
        g_list[cid - 1][p] = t;
        g_pos[t] = p;
    } else {
        g_pos[t] = -1;
    }
}

// ---------------- 3) head: 64-token tiles, 32 rows/block, k-chunked ----------
__global__ void __launch_bounds__(128, 4)
k_head(const int* __restrict__ target) {
    __shared__ unsigned long long shp[64][65];   // [k-pair][token], 33 KB
    __shared__ float red[4][64];
    int tile = blockIdx.x, chunk = blockIdx.y;
    int tid = threadIdx.x, warp = tid >> 5, lane = tid & 31;
    int t0 = tile * 64;
    int row0 = chunk * 32 + warp * 8;

    unsigned long long acc[8][2];
#pragma unroll
    for (int i = 0; i < 8; i++) { acc[i][0] = 0ull; acc[i][1] = 0ull; }

    for (int kc = 0; kc < 4; kc++) {
        __syncthreads();
        int kb = kc * 128 + tid;
#pragma unroll 4
        for (int tok = 0; tok < 64; tok++) {
            float v = g_hp0[(t0 + tok) * 512 + kb];
            ((float*)&shp[tid >> 1][tok])[tid & 1] = v;
        }
        __syncthreads();
        const float* wp = g_headW + (size_t)row0 * 512 + kc * 128;
#pragma unroll 2
        for (int k = 0; k < 128; k += 4) {
            int kp = k >> 1;
            unsigned long long a0 = shp[kp][lane];
            unsigned long long a1 = shp[kp][lane + 32];
            unsigned long long c0 = shp[kp + 1][lane];
            unsigned long long c1 = shp[kp + 1][lane + 32];
#pragma unroll
            for (int i = 0; i < 8; i++) {
                ulonglong2 w = *(const ulonglong2*)(wp + i * 512 + k);
                acc[i][0] = ffma2(a0, w.x, acc[i][0]);
                acc[i][0] = ffma2(c0, w.y, acc[i][0]);
                acc[i][1] = ffma2(a1, w.x, acc[i][1]);
                acc[i][1] = ffma2(c1, w.y, acc[i][1]);
            }
        }
    }
    // epilogue
    int tok0 = t0 + lane, tok1 = t0 + lane + 32;
    int tg0 = target[tok0], tg1 = target[tok1];
    int cid0 = (tg0 >= 20000) + (tg0 >= 40000) + (tg0 >= 200000);
    int cid1 = (tg1 >= 20000) + (tg1 >= 40000) + (tg1 >= 200000);
    int nc0 = cid0 ? (NHEAD - cid0) : tg0;
    int nc1 = cid1 ? (NHEAD - cid1) : tg1;
    float s0 = 0.f, s1 = 0.f;
#pragma unroll
    for (int i = 0; i < 8; i++) {
        int row = row0 + i;
        float bb = g_headB[row];
        float d0 = f2lo(acc[i][0]) + f2hi(acc[i][0]) + bb;
        float d1 = f2lo(acc[i][1]) + f2hi(acc[i][1]) + bb;
        if (row < NHEAD) { s0 += __expf(d0); s1 += __expf(d1); }
        if (row == nc0) g_nh[tok0] = d0;
        if (row == nc1) g_nh[tok1] = d1;
    }
    red[warp][lane] = s0;
    red[warp][lane + 32] = s1;
    __syncthreads();
    if (warp == 0) {
        float ta = red[0][lane] + red[1][lane] + red[2][lane] + red[3][lane];
        float tb = red[0][lane + 32] + red[1][lane + 32] + red[2][lane + 32] + red[3][lane + 32];
        g_ph[(size_t)tok0 * HCHUNKS + chunk] = ta;
        g_ph[(size_t)tok1 * HCHUNKS + chunk] = tb;
    }
}

// ---------------- 4) tails: compacted tokens, same loop shape ----------------
template <int E, int ROWS, int NCH, int CID, int OCC>
__global__ void __launch_bounds__(128, OCC)
k_tail(const float* __restrict__ Wa, const float* __restrict__ ba,
       const int* __restrict__ target) {
    constexpr int CROWS = 4 * ROWS;
    constexpr int KP = E / 2;
    __shared__ unsigned long long shp[KP][65];
    __shared__ float red[4][64];
    constexpr int c = CID - 1;
    const float* hp = (E == 128) ? g_hp1 : (E == 32) ? g_hp2 : g_hp3;
    const float* W = (CID == 3) ? g_W3p : Wa;
    const float* bias = (CID == 3) ? g_b3p : ba;
    float* gpt = (CID == 1) ? g_pt1 : (CID == 2) ? g_pt2 : g_pt3;
    constexpr int V = (CID == 1) ? 20000 : (CID == 2) ? 160000 : 67735;
    constexpr int L = (CID == 1) ? 20000 : (CID == 2) ? 40000 : 200000;

    int cnt = g_cnt[c];
    int tile = blockIdx.x;
    if (tile * 64 >= cnt) return;
    int chunk = blockIdx.y;
    int tid = threadIdx.x, warp = tid >> 5, lane = tid & 31;
    int row0 = chunk * CROWS + warp * ROWS;

    // stage 64 tokens of hp into [k-pair][token] layout
    {
        constexpr int WTOK = 128 / E;
        int tok_sub = tid / E;
        int k = tid % E;
#pragma unroll
        for (int base = 0; base < 64; base += WTOK) {
            int tok = base + tok_sub;
            int slot = tile * 64 + tok;
            int token = g_list[c][slot < cnt ? slot : cnt - 1];
            float v = hp[token * E + k];
            ((float*)&shp[k >> 1][tok])[k & 1] = v;
        }
    }
    __syncthreads();

    unsigned long long acc[ROWS][2];
#pragma unroll
    for (int i = 0; i < ROWS; i++) { acc[i][0] = 0ull; acc[i][1] = 0ull; }
    const float* wp = W + (size_t)row0 * E;
#pragma unroll 2
    for (int k = 0; k < E; k += 4) {
        int kp = k >> 1;
        unsigned long long a0 = shp[kp][lane];
        unsigned long long a1 = shp[kp][lane + 32];
        unsigned long long c0 = shp[kp + 1][lane];
        unsigned long long c1 = shp[kp + 1][lane + 32];
#pragma unroll
        for (int i = 0; i < ROWS; i++) {
            ulonglong2 w = *(const ulonglong2*)(wp + i * E + k);
            acc[i][0] = ffma2(a0, w.x, acc[i][0]);
            acc[i][0] = ffma2(c0, w.y, acc[i][0]);
            acc[i][1] = ffma2(a1, w.x, acc[i][1]);
            acc[i][1] = ffma2(c1, w.y, acc[i][1]);
        }
    }

    int slot0 = tile * 64 + lane, slot1 = slot0 + 32;
    int token0 = g_list[c][slot0 < cnt ? slot0 : cnt - 1];
    int token1 = g_list[c][slot1 < cnt ? slot1 : cnt - 1];
    int rel0 = target[token0] - L;
    int rel1 = target[token1] - L;
    float s0 = 0.f, s1 = 0.f;
#pragma unroll
    for (int i = 0; i < ROWS; i++) {
        int row = row0 + i;
        float bb = bias[row];
        float d0 = f2lo(acc[i][0]) + f2hi(acc[i][0]) + bb;
        float d1 = f2lo(acc[i][1]) + f2hi(acc[i][1]) + bb;
        if (row < V) { s0 += __expf(d0); s1 += __expf(d1); }
        if (row == rel0) g_nt[token0] = d0;
        if (row == rel1) g_nt[token1] = d1;
    }
    red[warp][lane] = s0;
    red[warp][lane + 32] = s1;
    __syncthreads();
    if (warp == 0) {
        float ta = red[0][lane] + red[1][lane] + red[2][lane] + red[3][lane];
        float tb = red[0][lane + 32] + red[1][lane + 32] + red[2][lane + 32] + red[3][lane + 32];
        gpt[(size_t)slot0 * NCH + chunk] = ta;
        gpt[(size_t)slot1 * NCH + chunk] = tb;
    }
}

// ---------------- 5) combine: warp per token ----------------
__global__ void k_comb(const int* __restrict__ target, float* __restrict__ out) {
    int t = (blockIdx.x * blockDim.x + threadIdx.x) >> 5;
    int lane = threadIdx.x & 31;
    if (t >= NTOK) return;
    float s = 0.f;
    for (int ch = lane; ch < HCHUNKS; ch += 32) s += g_ph[(size_t)t * HCHUNKS + ch];
#pragma unroll
    for (int o = 16; o; o >>= 1) s += __shfl_xor_sync(0xffffffffu, s, o);
    float hl = g_nh[t] - logf(s);
    int tg = target[t];
    int cid = (tg >= 20000) + (tg >= 40000) + (tg >= 200000);
    float nll = -hl;
    if (cid) {
        int p = g_pos[t];
        const float* pt;
        int nch;
        if (cid == 1) { pt = g_pt1 + (size_t)p * NCH1; nch = NCH1; }
        else if (cid == 2) { pt = g_pt2 + (size_t)p * NCH2; nch = NCH2; }
        else { pt = g_pt3 + (size_t)p * NCH3; nch = NCH3; }
        float st = 0.f;
        for (int ch = lane; ch < nch; ch += 32) st += pt[ch];
#pragma unroll
        for (int o = 16; o; o >>= 1) st += __shfl_xor_sync(0xffffffffu, st, o);
        nll = -(hl + g_nt[t] - logf(st));
    }
    if (lane == 0) out[t] = nll;
}

// ---------------- launch ----------------
extern "C" void kernel_launch(void* const* d_in, const int* in_sizes, int n_in,
                              void* d_out, int out_size) {
    const float* hidden = (const float*)d_in[0];
    const int*   target = (const int*)d_in[1];
    const float* W0 = (const float*)d_in[2];
    const float* b0 = (const float*)d_in[3];
    const float* p0 = (const float*)d_in[4];
    const float* W1 = (const float*)d_in[5];
    const float* b1 = (const float*)d_in[6];
    const float* p1 = (const float*)d_in[7];
    const float* W2 = (const float*)d_in[8];
    const float* b2 = (const float*)d_in[9];
    const float* p2 = (const float*)d_in[10];
    const float* W3 = (const float*)d_in[11];
    const float* b3 = (const float*)d_in[12];
    const float* p3 = (const float*)d_in[13];
    const float* CW = (const float*)d_in[14];
    const float* CB = (const float*)d_in[15];

    k_prep<<<2048, 256>>>((const float4*)W0, b0, (const float4*)CW, CB,
                          (const float4*)W3, b3);
    k_proj<<<NTOK / 8, 512>>>(hidden, p0, p1, p2, p3);
    k_compact<<<1, NTOK>>>(target);
    k_head<<<dim3(16, HCHUNKS), 128>>>(target);
    k_tail<128, 8,  NCH1, 1, 4><<<dim3(TILES1, NCH1), 128>>>(W1, b1, target);
    k_tail<32,  16, NCH2, 2, 3><<<dim3(TILES2, NCH2), 128>>>(W2, b2, target);
    k_tail<8,   8,  NCH3, 3, 4><<<dim3(TILES3, NCH3), 128>>>(W3, b3, target);
    k_comb<<<128, 256>>>(target, (float*)d_out);
}

// round 8
// speedup vs baseline: 1.0069x; 1.0069x over previous
#include <cuda_runtime.h>
#include <cstdint>

#define NTOK 1024
#define NHEAD 20003
#define HCHUNKS 626          // head row chunks of 32 (20032 rows padded)
#define NCH1 625             // tail1: 20000 / 32
#define NCH2 2500            // tail2: 160000 / 64
#define NCH3 2117            // tail3: ceil(67735/32), padded to 67744
#define V3PAD (NCH3 * 32)
#define TILES1 2
#define TILES2 11
#define TILES3 6

// ---------------- scratch (device globals; no allocs) ----------------
__device__ __align__(256) float g_headW[20032 * 512];   // W0 ++ CW ++ zero pad
__device__ __align__(256) float g_headB[20032];
__device__ __align__(256) float g_W3p[V3PAD * 8];
__device__ __align__(256) float g_b3p[V3PAD];
__device__ __align__(256) float g_hp0[NTOK * 512];
__device__ __align__(256) float g_hp1[NTOK * 128];
__device__ __align__(256) float g_hp2[NTOK * 32];
__device__ __align__(256) float g_hp3[NTOK * 8];
__device__ float g_ph[NTOK * HCHUNKS];
__device__ float g_nh[NTOK];
__device__ float g_nt[NTOK];
__device__ float g_pt1[TILES1 * 64 * NCH1];
__device__ float g_pt2[TILES2 * 64 * NCH2];
__device__ float g_pt3[TILES3 * 64 * NCH3];
__device__ int   g_pos[NTOK];
__device__ int   g_list[3][NTOK];
__device__ int   g_cnt[3];

// ---------------- f32x2 helpers ----------------
__device__ __forceinline__ unsigned long long ffma2(unsigned long long a,
                                                    unsigned long long b,
                                                    unsigned long long c) {
    unsigned long long d;
    asm("fma.rn.f32x2 %0, %1, %2, %3;" : "=l"(d) : "l"(a), "l"(b), "l"(c));
    return d;
}
__device__ __forceinline__ float f2lo(unsigned long long v) { return __uint_as_float((unsigned)v); }
__device__ __forceinline__ float f2hi(unsigned long long v) { return __uint_as_float((unsigned)(v >> 32)); }

// ---------------- 0) prep: pack head weights, pad W3 ----------------
__global__ void k_prep(const float4* __restrict__ W0, const float* __restrict__ b0,
                       const float4* __restrict__ CW, const float* __restrict__ CB,
                       const float4* __restrict__ W3, const float* __restrict__ b3) {
    int i = blockIdx.x * 256 + threadIdx.x;
    int stride = gridDim.x * 256;
    float4 z = make_float4(0.f, 0.f, 0.f, 0.f);
    float4* HW = (float4*)g_headW;
    for (int idx = i; idx < 20032 * 128; idx += stride) {
        float4 v = z;
        if (idx < 20000 * 128) v = W0[idx];
        else if (idx < NHEAD * 128) v = CW[idx - 20000 * 128];
        HW[idx] = v;
    }
    float4* W3P = (float4*)g_W3p;
    for (int idx = i; idx < V3PAD * 2; idx += stride)
        W3P[idx] = (idx < 67735 * 2) ? W3[idx] : z;
    for (int idx = i; idx < 20032; idx += stride)
        g_headB[idx] = (idx < 20000) ? b0[idx] : (idx < NHEAD ? CB[idx - 20000] : 0.f);
    for (int idx = i; idx < V3PAD; idx += stride)
        g_b3p[idx] = (idx < 67735) ? b3[idx] : 0.f;
}

// ---------------- 1) projections (8-token tiles) ----------------
__global__ void __launch_bounds__(512)
k_proj(const float* __restrict__ hidden,
       const float* __restrict__ p0, const float* __restrict__ p1,
       const float* __restrict__ p2, const float* __restrict__ p3) {
    __shared__ float h[8][512];
    int t0 = blockIdx.x * 8;
    int tid = threadIdx.x;
    for (int i = tid; i < 8 * 512; i += 512)
        h[i >> 9][i & 511] = hidden[(t0 + (i >> 9)) * 512 + (i & 511)];
    __syncthreads();
    {
        int j = tid;
        float a[8];
#pragma unroll
        for (int i = 0; i < 8; i++) a[i] = 0.f;
#pragma unroll 4
        for (int k = 0; k < 512; k++) {
            float w = p0[k * 512 + j];
#pragma unroll
            for (int i = 0; i < 8; i++) a[i] = fmaf(h[i][k], w, a[i]);
        }
#pragma unroll
        for (int i = 0; i < 8; i++) g_hp0[(t0 + i) * 512 + j] = a[i];
    }
    if (tid < 128) {
        int j = tid;
        float a[8];
#pragma unroll
        for (int i = 0; i < 8; i++) a[i] = 0.f;
#pragma unroll 4
        for (int k = 0; k < 512; k++) {
            float w = p1[k * 128 + j];
#pragma unroll
            for (int i = 0; i < 8; i++) a[i] = fmaf(h[i][k], w, a[i]);
        }
#pragma unroll
        for (int i = 0; i < 8; i++) g_hp1[(t0 + i) * 128 + j] = a[i];
    }
    if (tid < 32) {
        int j = tid;
        float a[8];
#pragma unroll
        for (int i = 0; i < 8; i++) a[i] = 0.f;
#pragma unroll 4
        for (int k = 0; k < 512; k++) {
            float w = p2[k * 32 + j];
#pragma unroll
            for (int i = 0; i < 8; i++) a[i] = fmaf(h[i][k], w, a[i]);
        }
#pragma unroll
        for (int i = 0; i < 8; i++) g_hp2[(t0 + i) * 32 + j] = a[i];
    }
    if (tid < 8) {
        int j = tid;
        float a[8];
#pragma unroll
        for (int i = 0; i < 8; i++) a[i] = 0.f;
#pragma unroll 4
        for (int k = 0; k < 512; k++) {
            float w = p3[k * 8 + j];
#pragma unroll
            for (int i = 0; i < 8; i++) a[i] = fmaf(h[i][k], w, a[i]);
        }
#pragma unroll
        for (int i = 0; i < 8; i++) g_hp3[(t0 + i) * 8 + j] = a[i];
    }
}

// ---------------- 2) cluster-id + compaction ----------------
__global__ void k_compact(const int* __restrict__ target) {
    int t = threadIdx.x;
    if (t < 3) g_cnt[t] = 0;
    __syncthreads();
    int tg = target[t];
    int cid = (tg >= 20000) + (tg >= 40000) + (tg >= 200000);
    if (cid > 0) {
        int p = atomicAdd(&g_cnt[cid - 1], 1);
        g_list[cid - 1][p] = t;
        g_pos[t] = p;
    } else {
        g_pos[t] = -1;
    }
}

// ---------------- 3) head: 64-token tiles, 32 rows/block, k-chunked ----------
__global__ void __launch_bounds__(128, 4)
k_head(const int* __restrict__ target) {
    __shared__ unsigned long long shp[64][65];   // [k-pair][token], 33 KB
    __shared__ float red[4][64];
    int tile = blockIdx.x, chunk = blockIdx.y;
    int tid = threadIdx.x, warp = tid >> 5, lane = tid & 31;
    int t0 = tile * 64;
    int row0 = chunk * 32 + warp * 8;

    unsigned long long acc[8][2];
#pragma unroll
    for (int i = 0; i < 8; i++) { acc[i][0] = 0ull; acc[i][1] = 0ull; }

    for (int kc = 0; kc < 4; kc++) {
        __syncthreads();
        int kb = kc * 128 + tid;
#pragma unroll 4
        for (int tok = 0; tok < 64; tok++) {
            float v = g_hp0[(t0 + tok) * 512 + kb];
            ((float*)&shp[tid >> 1][tok])[tid & 1] = v;
        }
        __syncthreads();
        const float* wp = g_headW + (size_t)row0 * 512 + kc * 128;
#pragma unroll 2
        for (int k = 0; k < 128; k += 4) {
            int kp = k >> 1;
            unsigned long long a0 = shp[kp][lane];
            unsigned long long a1 = shp[kp][lane + 32];
            unsigned long long c0 = shp[kp + 1][lane];
            unsigned long long c1 = shp[kp + 1][lane + 32];
#pragma unroll
            for (int i = 0; i < 8; i++) {
                ulonglong2 w = *(const ulonglong2*)(wp + i * 512 + k);
                acc[i][0] = ffma2(a0, w.x, acc[i][0]);
                acc[i][0] = ffma2(c0, w.y, acc[i][0]);
                acc[i][1] = ffma2(a1, w.x, acc[i][1]);
                acc[i][1] = ffma2(c1, w.y, acc[i][1]);
            }
        }
    }
    // epilogue
    int tok0 = t0 + lane, tok1 = t0 + lane + 32;
    int tg0 = target[tok0], tg1 = target[tok1];
    int cid0 = (tg0 >= 20000) + (tg0 >= 40000) + (tg0 >= 200000);
    int cid1 = (tg1 >= 20000) + (tg1 >= 40000) + (tg1 >= 200000);
    int nc0 = cid0 ? (NHEAD - cid0) : tg0;
    int nc1 = cid1 ? (NHEAD - cid1) : tg1;
    float s0 = 0.f, s1 = 0.f;
#pragma unroll
    for (int i = 0; i < 8; i++) {
        int row = row0 + i;
        float bb = g_headB[row];
        float d0 = f2lo(acc[i][0]) + f2hi(acc[i][0]) + bb;
        float d1 = f2lo(acc[i][1]) + f2hi(acc[i][1]) + bb;
        if (row < NHEAD) { s0 += __expf(d0); s1 += __expf(d1); }
        if (row == nc0) g_nh[tok0] = d0;
        if (row == nc1) g_nh[tok1] = d1;
    }
    red[warp][lane] = s0;
    red[warp][lane + 32] = s1;
    __syncthreads();
    if (warp == 0) {
        float ta = red[0][lane] + red[1][lane] + red[2][lane] + red[3][lane];
        float tb = red[0][lane + 32] + red[1][lane + 32] + red[2][lane + 32] + red[3][lane + 32];
        g_ph[(size_t)tok0 * HCHUNKS + chunk] = ta;
        g_ph[(size_t)tok1 * HCHUNKS + chunk] = tb;
    }
}

// ---------------- 4) tails: compacted tokens, same loop shape ----------------
template <int E, int ROWS, int NCH, int CID, int OCC>
__global__ void __launch_bounds__(128, OCC)
k_tail(const float* __restrict__ Wa, const float* __restrict__ ba,
       const int* __restrict__ target) {
    constexpr int CROWS = 4 * ROWS;
    constexpr int KP = E / 2;
    __shared__ unsigned long long shp[KP][65];
    __shared__ float red[4][64];
    constexpr int c = CID - 1;
    const float* hp = (E == 128) ? g_hp1 : (E == 32) ? g_hp2 : g_hp3;
    const float* W = (CID == 3) ? g_W3p : Wa;
    const float* bias = (CID == 3) ? g_b3p : ba;
    float* gpt = (CID == 1) ? g_pt1 : (CID == 2) ? g_pt2 : g_pt3;
    constexpr int V = (CID == 1) ? 20000 : (CID == 2) ? 160000 : 67735;
    constexpr int L = (CID == 1) ? 20000 : (CID == 2) ? 40000 : 200000;

    int cnt = g_cnt[c];
    int tile = blockIdx.x;
    if (tile * 64 >= cnt) return;
    int chunk = blockIdx.y;
    int tid = threadIdx.x, warp = tid >> 5, lane = tid & 31;
    int row0 = chunk * CROWS + warp * ROWS;

    // stage 64 tokens of hp into [k-pair][token] layout
    {
        constexpr int WTOK = 128 / E;
        int tok_sub = tid / E;
        int k = tid % E;
#pragma unroll
        for (int base = 0; base < 64; base += WTOK) {
            int tok = base + tok_sub;
            int slot = tile * 64 + tok;
            int token = g_list[c][slot < cnt ? slot : cnt - 1];
            float v = hp[token * E + k];
            ((float*)&shp[k >> 1][tok])[k & 1] = v;
        }
    }
    __syncthreads();

    unsigned long long acc[ROWS][2];
#pragma unroll
    for (int i = 0; i < ROWS; i++) { acc[i][0] = 0ull; acc[i][1] = 0ull; }
    const float* wp = W + (size_t)row0 * E;
#pragma unroll 2
    for (int k = 0; k < E; k += 4) {
        int kp = k >> 1;
        unsigned long long a0 = shp[kp][lane];
        unsigned long long a1 = shp[kp][lane + 32];
        unsigned long long c0 = shp[kp + 1][lane];
        unsigned long long c1 = shp[kp + 1][lane + 32];
#pragma unroll
        for (int i = 0; i < ROWS; i++) {
            ulonglong2 w = *(const ulonglong2*)(wp + i * E + k);
            acc[i][0] = ffma2(a0, w.x, acc[i][0]);
            acc[i][0] = ffma2(c0, w.y, acc[i][0]);
            acc[i][1] = ffma2(a1, w.x, acc[i][1]);
            acc[i][1] = ffma2(c1, w.y, acc[i][1]);
        }
    }

    int slot0 = tile * 64 + lane, slot1 = slot0 + 32;
    int token0 = g_list[c][slot0 < cnt ? slot0 : cnt - 1];
    int token1 = g_list[c][slot1 < cnt ? slot1 : cnt - 1];
    int rel0 = target[token0] - L;
    int rel1 = target[token1] - L;
    float s0 = 0.f, s1 = 0.f;
#pragma unroll
    for (int i = 0; i < ROWS; i++) {
        int row = row0 + i;
        float bb = bias[row];
        float d0 = f2lo(acc[i][0]) + f2hi(acc[i][0]) + bb;
        float d1 = f2lo(acc[i][1]) + f2hi(acc[i][1]) + bb;
        if (row < V) { s0 += __expf(d0); s1 += __expf(d1); }
        if (row == rel0) g_nt[token0] = d0;
        if (row == rel1) g_nt[token1] = d1;
    }
    red[warp][lane] = s0;
    red[warp][lane + 32] = s1;
    __syncthreads();
    if (warp == 0) {
        float ta = red[0][lane] + red[1][lane] + red[2][lane] + red[3][lane];
        float tb = red[0][lane + 32] + red[1][lane + 32] + red[2][lane + 32] + red[3][lane + 32];
        gpt[(size_t)slot0 * NCH + chunk] = ta;
        gpt[(size_t)slot1 * NCH + chunk] = tb;
    }
}

// ---------------- 5) combine: warp per token ----------------
__global__ void k_comb(const int* __restrict__ target, float* __restrict__ out) {
    int t = (blockIdx.x * blockDim.x + threadIdx.x) >> 5;
    int lane = threadIdx.x & 31;
    if (t >= NTOK) return;
    float s = 0.f;
    for (int ch = lane; ch < HCHUNKS; ch += 32) s += g_ph[(size_t)t * HCHUNKS + ch];
#pragma unroll
    for (int o = 16; o; o >>= 1) s += __shfl_xor_sync(0xffffffffu, s, o);
    float hl = g_nh[t] - logf(s);
    int tg = target[t];
    int cid = (tg >= 20000) + (tg >= 40000) + (tg >= 200000);
    float nll = -hl;
    if (cid) {
        int p = g_pos[t];
        const float* pt;
        int nch;
        if (cid == 1) { pt = g_pt1 + (size_t)p * NCH1; nch = NCH1; }
        else if (cid == 2) { pt = g_pt2 + (size_t)p * NCH2; nch = NCH2; }
        else { pt = g_pt3 + (size_t)p * NCH3; nch = NCH3; }
        float st = 0.f;
        for (int ch = lane; ch < nch; ch += 32) st += pt[ch];
#pragma unroll
        for (int o = 16; o; o >>= 1) st += __shfl_xor_sync(0xffffffffu, st, o);
        nll = -(hl + g_nt[t] - logf(st));
    }
    if (lane == 0) out[t] = nll;
}

// ---------------- launch ----------------
extern "C" void kernel_launch(void* const* d_in, const int* in_sizes, int n_in,
                              void* d_out, int out_size) {
    const float* hidden = (const float*)d_in[0];
    const int*   target = (const int*)d_in[1];
    const float* W0 = (const float*)d_in[2];
    const float* b0 = (const float*)d_in[3];
    const float* p0 = (const float*)d_in[4];
    const float* W1 = (const float*)d_in[5];
    const float* b1 = (const float*)d_in[6];
    const float* p1 = (const float*)d_in[7];
    const float* W2 = (const float*)d_in[8];
    const float* b2 = (const float*)d_in[9];
    const float* p2 = (const float*)d_in[10];
    const float* W3 = (const float*)d_in[11];
    const float* b3 = (const float*)d_in[12];
    const float* p3 = (const float*)d_in[13];
    const float* CW = (const float*)d_in[14];
    const float* CB = (const float*)d_in[15];

    k_prep<<<2048, 256>>>((const float4*)W0, b0, (const float4*)CW, CB,
                          (const float4*)W3, b3);
    k_proj<<<NTOK / 8, 512>>>(hidden, p0, p1, p2, p3);
    k_compact<<<1, NTOK>>>(target);
    k_head<<<dim3(16, HCHUNKS), 128>>>(target);
    k_tail<128, 8,  NCH1, 1, 4><<<dim3(TILES1, NCH1), 128>>>(W1, b1, target);
    k_tail<32,  16, NCH2, 2, 3><<<dim3(TILES2, NCH2), 128>>>(W2, b2, target);
    k_tail<8,   8,  NCH3, 3, 4><<<dim3(TILES3, NCH3), 128>>>(W3, b3, target);
    k_comb<<<128, 256>>>(target, (float*)d_out);
}

// round 15
// speedup vs baseline: 1.8170x; 1.8046x over previous
#include <cuda_runtime.h>
#include <cuda_bf16.h>
#include <cstdint>

#define NTOK 1024
#define NHEAD 20003
#define NHPAD 20096          // 157 * 128
#define HCHUNKS 157          // head row chunks of 128
#define KPRIME 1536          // 3 * 512 (hi/lo-split K dimension)
#define NCH1 625             // tail1: 20000 / 32
#define NCH2 2500            // tail2: 160000 / 64
#define NCH3 2117            // tail3: ceil(67735/32)
#define V3PAD (NCH3 * 32)
#define TILES1 2
#define TILES2 11
#define TILES3 6

#define PITCH 72             // bf16 units per smem row (64 data + 8 pad) = 144 B
#define SMHALF (128 * PITCH) // bf16 units per (matrix, buffer)
#define SM_TOT (4 * SMHALF * 2)  // sA[2] + sB[2], bytes = 73728

// ---------------- scratch (device globals; no allocs) ----------------
__device__ __align__(256) __nv_bfloat16 g_Weff[(size_t)NHPAD * KPRIME]; // (wh,wl,wh)
__device__ __align__(256) __nv_bfloat16 g_Aeff[(size_t)NTOK * KPRIME];  // (ah,ah,al)
__device__ __align__(256) float g_headB[NHPAD];
__device__ __align__(256) float g_W3p[V3PAD * 8];
__device__ __align__(256) float g_b3p[V3PAD];
__device__ __align__(256) float g_hp1[NTOK * 128];
__device__ __align__(256) float g_hp2[NTOK * 32];
__device__ __align__(256) float g_hp3[NTOK * 8];
__device__ float g_ph[NTOK * HCHUNKS];
__device__ float g_nh[NTOK];
__device__ float g_nt[NTOK];
__device__ float g_pt1[TILES1 * 64 * NCH1];
__device__ float g_pt2[TILES2 * 64 * NCH2];
__device__ float g_pt3[TILES3 * 64 * NCH3];
__device__ int   g_pos[NTOK];
__device__ int   g_list[3][NTOK];
__device__ int   g_cnt[3];

// ---------------- helpers ----------------
__device__ __forceinline__ uint32_t smem_u32(const void* p) {
    uint32_t a;
    asm("{ .reg .u64 t; cvta.to.shared.u64 t, %1; cvt.u32.u64 %0, t; }" : "=r"(a) : "l"(p));
    return a;
}
__device__ __forceinline__ void ldsm4(uint32_t& r0, uint32_t& r1, uint32_t& r2,
                                      uint32_t& r3, uint32_t addr) {
    asm volatile("ldmatrix.sync.aligned.m8n8.x4.shared.b16 {%0,%1,%2,%3}, [%4];"
                 : "=r"(r0), "=r"(r1), "=r"(r2), "=r"(r3) : "r"(addr));
}
__device__ __forceinline__ void mma16816(float& c0, float& c1, float& c2, float& c3,
                                         uint32_t a0, uint32_t a1, uint32_t a2, uint32_t a3,
                                         uint32_t b0, uint32_t b1) {
    asm volatile(
        "mma.sync.aligned.m16n8k16.row.col.f32.bf16.bf16.f32 "
        "{%0,%1,%2,%3}, {%4,%5,%6,%7}, {%8,%9}, {%0,%1,%2,%3};"
        : "+f"(c0), "+f"(c1), "+f"(c2), "+f"(c3)
        : "r"(a0), "r"(a1), "r"(a2), "r"(a3), "r"(b0), "r"(b1));
}

// f32x2 helpers (scalar tails)
__device__ __forceinline__ unsigned long long ffma2(unsigned long long a,
                                                    unsigned long long b,
                                                    unsigned long long c) {
    unsigned long long d;
    asm("fma.rn.f32x2 %0, %1, %2, %3;" : "=l"(d) : "l"(a), "l"(b), "l"(c));
    return d;
}
__device__ __forceinline__ float f2lo(unsigned long long v) { return __uint_as_float((unsigned)v); }
__device__ __forceinline__ float f2hi(unsigned long long v) { return __uint_as_float((unsigned)(v >> 32)); }

// ---------------- 0) prep: Weff hi/lo-interleave, bias, W3 pad ---------------
__global__ void k_prep(const float* __restrict__ W0, const float* __restrict__ b0,
                       const float* __restrict__ CW, const float* __restrict__ CB,
                       const float4* __restrict__ W3, const float* __restrict__ b3) {
    int i = blockIdx.x * 256 + threadIdx.x;
    int stride = gridDim.x * 256;
    // each thread handles 8 consecutive k of one row -> 24 bf16 = 3x16B stores
    for (int q = i; q < NHPAD * 64; q += stride) {
        int row = q >> 6;
        int k8 = (q & 63) << 3;
        float v[8];
#pragma unroll
        for (int j = 0; j < 8; j++) {
            int k = k8 + j;
            float w = 0.f;
            if (row < 20000) w = W0[(size_t)row * 512 + k];
            else if (row < NHEAD) w = CW[(size_t)(row - 20000) * 512 + k];
            v[j] = w;
        }
        __nv_bfloat16 tmp[24];
#pragma unroll
        for (int j = 0; j < 8; j++) {
            __nv_bfloat16 hi = __float2bfloat16(v[j]);
            __nv_bfloat16 lo = __float2bfloat16(v[j] - __bfloat162float(hi));
            tmp[3 * j] = hi; tmp[3 * j + 1] = lo; tmp[3 * j + 2] = hi;
        }
        uint4* dst = (uint4*)(g_Weff + (size_t)row * KPRIME + 3 * k8);
        const uint4* src = (const uint4*)tmp;
        dst[0] = src[0]; dst[1] = src[1]; dst[2] = src[2];
    }
    float4 z = make_float4(0.f, 0.f, 0.f, 0.f);
    float4* W3P = (float4*)g_W3p;
    for (int idx = i; idx < V3PAD * 2; idx += stride)
        W3P[idx] = (idx < 67735 * 2) ? W3[idx] : z;
    for (int idx = i; idx < NHPAD; idx += stride)
        g_headB[idx] = (idx < 20000) ? b0[idx] : (idx < NHEAD ? CB[idx - 20000] : -1e30f);
    for (int idx = i; idx < V3PAD; idx += stride)
        g_b3p[idx] = (idx < 67735) ? b3[idx] : 0.f;
}

// ---------------- 1) projections (8-token tiles); hp0 -> Aeff ----------------
__global__ void __launch_bounds__(512)
k_proj(const float* __restrict__ hidden,
       const float* __restrict__ p0, const float* __restrict__ p1,
       const float* __restrict__ p2, const float* __restrict__ p3) {
    __shared__ float h[8][512];
    int t0 = blockIdx.x * 8;
    int tid = threadIdx.x;
    for (int i = tid; i < 8 * 512; i += 512)
        h[i >> 9][i & 511] = hidden[(t0 + (i >> 9)) * 512 + (i & 511)];
    __syncthreads();
    {
        int j = tid;   // k index
        float a[8];
#pragma unroll
        for (int i = 0; i < 8; i++) a[i] = 0.f;
#pragma unroll 4
        for (int k = 0; k < 512; k++) {
            float w = p0[k * 512 + j];
#pragma unroll
            for (int i = 0; i < 8; i++) a[i] = fmaf(h[i][k], w, a[i]);
        }
#pragma unroll
        for (int i = 0; i < 8; i++) {
            __nv_bfloat16 hi = __float2bfloat16(a[i]);
            __nv_bfloat16 lo = __float2bfloat16(a[i] - __bfloat162float(hi));
            size_t base = (size_t)(t0 + i) * KPRIME + 3 * j;
            g_Aeff[base] = hi; g_Aeff[base + 1] = hi; g_Aeff[base + 2] = lo;
        }
    }
    if (tid < 128) {
        int j = tid;
        float a[8];
#pragma unroll
        for (int i = 0; i < 8; i++) a[i] = 0.f;
#pragma unroll 4
        for (int k = 0; k < 512; k++) {
            float w = p1[k * 128 + j];
#pragma unroll
            for (int i = 0; i < 8; i++) a[i] = fmaf(h[i][k], w, a[i]);
        }
#pragma unroll
        for (int i = 0; i < 8; i++) g_hp1[(t0 + i) * 128 + j] = a[i];
    }
    if (tid < 32) {
        int j = tid;
        float a[8];
#pragma unroll
        for (int i = 0; i < 8; i++) a[i] = 0.f;
#pragma unroll 4
        for (int k = 0; k < 512; k++) {
            float w = p2[k * 32 + j];
#pragma unroll
            for (int i = 0; i < 8; i++) a[i] = fmaf(h[i][k], w, a[i]);
        }
#pragma unroll
        for (int i = 0; i < 8; i++) g_hp2[(t0 + i) * 32 + j] = a[i];
    }
    if (tid < 8) {
        int j = tid;
        float a[8];
#pragma unroll
        for (int i = 0; i < 8; i++) a[i] = 0.f;
#pragma unroll 4
        for (int k = 0; k < 512; k++) {
            float w = p3[k * 8 + j];
#pragma unroll
            for (int i = 0; i < 8; i++) a[i] = fmaf(h[i][k], w, a[i]);
        }
#pragma unroll
        for (int i = 0; i < 8; i++) g_hp3[(t0 + i) * 8 + j] = a[i];
    }
}

// ---------------- 2) cluster-id + compaction ----------------
__global__ void k_compact(const int* __restrict__ target) {
    int t = threadIdx.x;
    if (t < 3) g_cnt[t] = 0;
    __syncthreads();
    int tg = target[t];
    int cid = (tg >= 20000) + (tg >= 40000) + (tg >= 200000);
    if (cid > 0) {
        int p = atomicAdd(&g_cnt[cid - 1], 1);
        g_list[cid - 1][p] = t;
        g_pos[t] = p;
    } else {
        g_pos[t] = -1;
    }
}

// ---------------- 3) head via mma.sync bf16: 128 tok x 128 rows per CTA ------
extern __shared__ __nv_bfloat16 hsm[];
__global__ void __launch_bounds__(256, 2)
k_head_mma(const int* __restrict__ target) {
    const int tid = threadIdx.x, wid = tid >> 5, lane = tid & 31;
    const int tile = blockIdx.x, chunk = blockIdx.y;
    const int t0 = tile * 128, row0 = chunk * 128;
    const int wm = (wid & 1) * 64;    // warp m (token) offset
    const int wn = (wid >> 1) * 32;   // warp n (row) offset

    __nv_bfloat16* sA = hsm;                    // [2][128*PITCH]
    __nv_bfloat16* sB = hsm + 2 * SMHALF;
    const uint32_t sbA = smem_u32(sA);
    const uint32_t sbB = smem_u32(sB);

    // ldmatrix per-lane bases
    const int rowA = wm + ((lane >> 3) & 1) * 8 + (lane & 7);
    const int kA = (lane >> 4) * 8;
    const int rowB = wn + (lane >> 4) * 8 + (lane & 7);
    const int kB = ((lane >> 3) & 1) * 8;

    float acc[4][4][4];
#pragma unroll
    for (int mt = 0; mt < 4; mt++)
#pragma unroll
        for (int nt = 0; nt < 4; nt++)
#pragma unroll
            for (int v = 0; v < 4; v++) acc[mt][nt][v] = 0.f;

    const __nv_bfloat16* gA = g_Aeff + (size_t)t0 * KPRIME;
    const __nv_bfloat16* gB = g_Weff + (size_t)row0 * KPRIME;

    // stage chunk 0
#pragma unroll
    for (int j = 0; j < 4; j++) {
        int flat = tid + 256 * j;           // 0..1023 16B-chunks
        int r = flat >> 3, ku = (flat & 7) * 8;
        *(float4*)(sA + r * PITCH + ku) = *(const float4*)(gA + (size_t)r * KPRIME + ku);
        *(float4*)(sB + r * PITCH + ku) = *(const float4*)(gB + (size_t)r * KPRIME + ku);
    }

    for (int kc = 0; kc < 24; kc++) {
        __syncthreads();
        int buf = kc & 1;
        if (kc + 1 < 24) {
            int nb = buf ^ 1;
            const __nv_bfloat16* gA2 = gA + (kc + 1) * 64;
            const __nv_bfloat16* gB2 = gB + (kc + 1) * 64;
#pragma unroll
            for (int j = 0; j < 4; j++) {
                int flat = tid + 256 * j;
                int r = flat >> 3, ku = (flat & 7) * 8;
                *(float4*)(sA + nb * SMHALF + r * PITCH + ku) =
                    *(const float4*)(gA2 + (size_t)r * KPRIME + ku);
                *(float4*)(sB + nb * SMHALF + r * PITCH + ku) =
                    *(const float4*)(gB2 + (size_t)r * KPRIME + ku);
            }
        }
        uint32_t baseA = sbA + buf * (SMHALF * 2);
        uint32_t baseB = sbB + buf * (SMHALF * 2);
#pragma unroll
        for (int ks = 0; ks < 4; ks++) {
            uint32_t a[4][4];
#pragma unroll
            for (int mt = 0; mt < 4; mt++) {
                uint32_t ad = baseA + ((rowA + mt * 16) * PITCH + ks * 16 + kA) * 2;
                ldsm4(a[mt][0], a[mt][1], a[mt][2], a[mt][3], ad);
            }
            uint32_t b[4][2];
#pragma unroll
            for (int p = 0; p < 2; p++) {
                uint32_t bd = baseB + ((rowB + p * 16) * PITCH + ks * 16 + kB) * 2;
                uint32_t r0, r1, r2, r3;
                ldsm4(r0, r1, r2, r3, bd);
                b[2 * p][0] = r0; b[2 * p][1] = r1;
                b[2 * p + 1][0] = r2; b[2 * p + 1][1] = r3;
            }
#pragma unroll
            for (int mt = 0; mt < 4; mt++)
#pragma unroll
                for (int nt = 0; nt < 4; nt++)
                    mma16816(acc[mt][nt][0], acc[mt][nt][1], acc[mt][nt][2], acc[mt][nt][3],
                             a[mt][0], a[mt][1], a[mt][2], a[mt][3],
                             b[nt][0], b[nt][1]);
        }
    }
    __syncthreads();

    // epilogue
    float bias_v[4][2];
#pragma unroll
    for (int nt = 0; nt < 4; nt++)
#pragma unroll
        for (int odd = 0; odd < 2; odd++)
            bias_v[nt][odd] = g_headB[row0 + wn + nt * 8 + ((lane & 3) << 1) + odd];

    float* red = (float*)hsm;   // [128][17]
    int colw = ((wid >> 1) << 2) | (lane & 3);
#pragma unroll
    for (int mt = 0; mt < 4; mt++)
#pragma unroll
        for (int half = 0; half < 2; half++) {
            int tokl = wm + mt * 16 + (lane >> 2) + half * 8;
            int tok = t0 + tokl;
            int tg = target[tok];
            int cid = (tg >= 20000) + (tg >= 40000) + (tg >= 200000);
            int nc = cid ? (NHEAD - cid) : tg;
            float s = 0.f;
#pragma unroll
            for (int nt = 0; nt < 4; nt++)
#pragma unroll
                for (int odd = 0; odd < 2; odd++) {
                    int row = row0 + wn + nt * 8 + ((lane & 3) << 1) + odd;
                    float lg = acc[mt][nt][half * 2 + odd] + bias_v[nt][odd];
                    s += __expf(lg);
                    if (row == nc) g_nh[tok] = lg;
                }
            red[tokl * 17 + colw] = s;
        }
    __syncthreads();
    if (tid < 128) {
        float s = 0.f;
#pragma unroll
        for (int c = 0; c < 16; c++) s += red[tid * 17 + c];
        g_ph[(size_t)(t0 + tid) * HCHUNKS + chunk] = s;
    }
}

// ---------------- 4) tails: scalar FFMA2 (as R8, passing) ----------------
template <int E, int ROWS, int NCH, int CID, int OCC>
__global__ void __launch_bounds__(128, OCC)
k_tail(const float* __restrict__ Wa, const float* __restrict__ ba,
       const int* __restrict__ target) {
    constexpr int CROWS = 4 * ROWS;
    constexpr int KP = E / 2;
    __shared__ unsigned long long shp[KP][65];
    __shared__ float red[4][64];
    constexpr int c = CID - 1;
    const float* hp = (E == 128) ? g_hp1 : (E == 32) ? g_hp2 : g_hp3;
    const float* W = (CID == 3) ? g_W3p : Wa;
    const float* bias = (CID == 3) ? g_b3p : ba;
    float* gpt = (CID == 1) ? g_pt1 : (CID == 2) ? g_pt2 : g_pt3;
    constexpr int V = (CID == 1) ? 20000 : (CID == 2) ? 160000 : 67735;
    constexpr int L = (CID == 1) ? 20000 : (CID == 2) ? 40000 : 200000;

    int cnt = g_cnt[c];
    int tile = blockIdx.x;
    if (tile * 64 >= cnt) return;
    int chunk = blockIdx.y;
    int tid = threadIdx.x, warp = tid >> 5, lane = tid & 31;
    int row0 = chunk * CROWS + warp * ROWS;

    {
        constexpr int WTOK = 128 / E;
        int tok_sub = tid / E;
        int k = tid % E;
#pragma unroll
        for (int base = 0; base < 64; base += WTOK) {
            int tok = base + tok_sub;
            int slot = tile * 64 + tok;
            int token = g_list[c][slot < cnt ? slot : cnt - 1];
            float v = hp[token * E + k];
            ((float*)&shp[k >> 1][tok])[k & 1] = v;
        }
    }
    __syncthreads();

    unsigned long long acc[ROWS][2];
#pragma unroll
    for (int i = 0; i < ROWS; i++) { acc[i][0] = 0ull; acc[i][1] = 0ull; }
    const float* wp = W + (size_t)row0 * E;
#pragma unroll 2
    for (int k = 0; k < E; k += 4) {
        int kp = k >> 1;
        unsigned long long a0 = shp[kp][lane];
        unsigned long long a1 = shp[kp][lane + 32];
        unsigned long long c0 = shp[kp + 1][lane];
        unsigned long long c1 = shp[kp + 1][lane + 32];
#pragma unroll
        for (int i = 0; i < ROWS; i++) {
            ulonglong2 w = *(const ulonglong2*)(wp + i * E + k);
            acc[i][0] = ffma2(a0, w.x, acc[i][0]);
            acc[i][0] = ffma2(c0, w.y, acc[i][0]);
            acc[i][1] = ffma2(a1, w.x, acc[i][1]);
            acc[i][1] = ffma2(c1, w.y, acc[i][1]);
        }
    }

    int slot0 = tile * 64 + lane, slot1 = slot0 + 32;
    int token0 = g_list[c][slot0 < cnt ? slot0 : cnt - 1];
    int token1 = g_list[c][slot1 < cnt ? slot1 : cnt - 1];
    int rel0 = target[token0] - L;
    int rel1 = target[token1] - L;
    float s0 = 0.f, s1 = 0.f;
#pragma unroll
    for (int i = 0; i < ROWS; i++) {
        int row = row0 + i;
        float bb = bias[row];
        float d0 = f2lo(acc[i][0]) + f2hi(acc[i][0]) + bb;
        float d1 = f2lo(acc[i][1]) + f2hi(acc[i][1]) + bb;
        if (row < V) { s0 += __expf(d0); s1 += __expf(d1); }
        if (row == rel0) g_nt[token0] = d0;
        if (row == rel1) g_nt[token1] = d1;
    }
    red[warp][lane] = s0;
    red[warp][lane + 32] = s1;
    __syncthreads();
    if (warp == 0) {
        float ta = red[0][lane] + red[1][lane] + red[2][lane] + red[3][lane];
        float tb = red[0][lane + 32] + red[1][lane + 32] + red[2][lane + 32] + red[3][lane + 32];
        gpt[(size_t)slot0 * NCH + chunk] = ta;
        gpt[(size_t)slot1 * NCH + chunk] = tb;
    }
}

// ---------------- 5) combine: warp per token ----------------
__global__ void k_comb(const int* __restrict__ target, float* __restrict__ out) {
    int t = (blockIdx.x * blockDim.x + threadIdx.x) >> 5;
    int lane = threadIdx.x & 31;
    if (t >= NTOK) return;
    float s = 0.f;
    for (int ch = lane; ch < HCHUNKS; ch += 32) s += g_ph[(size_t)t * HCHUNKS + ch];
#pragma unroll
    for (int o = 16; o; o >>= 1) s += __shfl_xor_sync(0xffffffffu, s, o);
    float hl = g_nh[t] - logf(s);
    int tg = target[t];
    int cid = (tg >= 20000) + (tg >= 40000) + (tg >= 200000);
    float nll = -hl;
    if (cid) {
        int p = g_pos[t];
        const float* pt;
        int nch;
        if (cid == 1) { pt = g_pt1 + (size_t)p * NCH1; nch = NCH1; }
        else if (cid == 2) { pt = g_pt2 + (size_t)p * NCH2; nch = NCH2; }
        else { pt = g_pt3 + (size_t)p * NCH3; nch = NCH3; }
        float st = 0.f;
        for (int ch = lane; ch < nch; ch += 32) st += pt[ch];
#pragma unroll
        for (int o = 16; o; o >>= 1) st += __shfl_xor_sync(0xffffffffu, st, o);
        nll = -(hl + g_nt[t] - logf(st));
    }
    if (lane == 0) out[t] = nll;
}

// ---------------- launch ----------------
extern "C" void kernel_launch(void* const* d_in, const int* in_sizes, int n_in,
                              void* d_out, int out_size) {
    const float* hidden = (const float*)d_in[0];
    const int*   target = (const int*)d_in[1];
    const float* W0 = (const float*)d_in[2];
    const float* b0 = (const float*)d_in[3];
    const float* p0 = (const float*)d_in[4];
    const float* W1 = (const float*)d_in[5];
    const float* b1 = (const float*)d_in[6];
    const float* p1 = (const float*)d_in[7];
    const float* W2 = (const float*)d_in[8];
    const float* b2 = (const float*)d_in[9];
    const float* p2 = (const float*)d_in[10];
    const float* W3 = (const float*)d_in[11];
    const float* b3 = (const float*)d_in[12];
    const float* p3 = (const float*)d_in[13];
    const float* CW = (const float*)d_in[14];
    const float* CB = (const float*)d_in[15];

    cudaFuncSetAttribute(k_head_mma, cudaFuncAttributeMaxDynamicSharedMemorySize, SM_TOT);

    k_prep<<<2048, 256>>>(W0, b0, CW, CB, (const float4*)W3, b3);
    k_proj<<<NTOK / 8, 512>>>(hidden, p0, p1, p2, p3);
    k_compact<<<1, NTOK>>>(target);
    k_head_mma<<<dim3(8, HCHUNKS), 256, SM_TOT>>>(target);
    k_tail<128, 8,  NCH1, 1, 4><<<dim3(TILES1, NCH1), 128>>>(W1, b1, target);
    k_tail<32,  16, NCH2, 2, 3><<<dim3(TILES2, NCH2), 128>>>(W2, b2, target);
    k_tail<8,   8,  NCH3, 3, 4><<<dim3(TILES3, NCH3), 128>>>(W3, b3, target);
    k_comb<<<128, 256>>>(target, (float*)d_out);
}

// round 17
// speedup vs baseline: 2.1858x; 1.2030x over previous
#include <cuda_runtime.h>
#include <cuda_bf16.h>
#include <cstdint>

#define NTOK 1024
#define NHEAD 20003
#define NHPAD 20096          // 157 * 128
#define HCHUNKS 157          // head row chunks of 128
#define KPH 1536             // head K' = 3*512
// tail1 (MMA): K=128 -> K'=384, rows padded to 20096
#define N1PAD 20096
#define KP1 384
#define NCH1T 157
#define CAP1 256
// tail2 (MMA): K=32 -> K'=96 padded to 128, rows 160000 exact
#define KP2 128
#define NCH2T 1250
#define CAP2 768
// tail3 scalar
#define NCH3 2117
#define V3PAD (NCH3 * 32)
#define TILES3 6

#define PITCH 72             // bf16 per smem row (64 data + 8 pad) = 144 B
#define SMHALF (128 * PITCH)
#define SM_TOT (4 * SMHALF * 2)  // 73728 B

// ---------------- scratch (device globals; no allocs) ----------------
__device__ __align__(256) __nv_bfloat16 g_Weff[(size_t)NHPAD * KPH];
__device__ __align__(256) __nv_bfloat16 g_W1eff[(size_t)N1PAD * KP1];
__device__ __align__(256) __nv_bfloat16 g_W2eff[(size_t)160000 * KP2];
__device__ __align__(256) __nv_bfloat16 g_Aeff[(size_t)NTOK * KPH];
__device__ __align__(256) __nv_bfloat16 g_A1eff[(size_t)CAP1 * KP1];
__device__ __align__(256) __nv_bfloat16 g_A2eff[(size_t)CAP2 * KP2];
__device__ __align__(256) float g_headB[NHPAD];
__device__ __align__(256) float g_b1p[N1PAD];
__device__ __align__(256) float g_W3p[V3PAD * 8];
__device__ __align__(256) float g_b3p[V3PAD];
__device__ __align__(256) float g_hp1[NTOK * 128];
__device__ __align__(256) float g_hp2[NTOK * 32];
__device__ __align__(256) float g_hp3[NTOK * 8];
__device__ float g_ph[NTOK * HCHUNKS];
__device__ float g_nh[NTOK];
__device__ float g_nt[NTOK];
__device__ float g_pt1[CAP1 * NCH1T];
__device__ float g_pt2[CAP2 * NCH2T];
__device__ float g_pt3[TILES3 * 64 * NCH3];
__device__ int   g_pos[NTOK];
__device__ int   g_list[3][NTOK];
__device__ int   g_cnt[3];

// ---------------- helpers ----------------
__device__ __forceinline__ uint32_t smem_u32(const void* p) {
    uint32_t a;
    asm("{ .reg .u64 t; cvta.to.shared.u64 t, %1; cvt.u32.u64 %0, t; }" : "=r"(a) : "l"(p));
    return a;
}
__device__ __forceinline__ void ldsm4(uint32_t& r0, uint32_t& r1, uint32_t& r2,
                                      uint32_t& r3, uint32_t addr) {
    asm volatile("ldmatrix.sync.aligned.m8n8.x4.shared.b16 {%0,%1,%2,%3}, [%4];"
                 : "=r"(r0), "=r"(r1), "=r"(r2), "=r"(r3) : "r"(addr));
}
__device__ __forceinline__ void mma16816(float& c0, float& c1, float& c2, float& c3,
                                         uint32_t a0, uint32_t a1, uint32_t a2, uint32_t a3,
                                         uint32_t b0, uint32_t b1) {
    asm volatile(
        "mma.sync.aligned.m16n8k16.row.col.f32.bf16.bf16.f32 "
        "{%0,%1,%2,%3}, {%4,%5,%6,%7}, {%8,%9}, {%0,%1,%2,%3};"
        : "+f"(c0), "+f"(c1), "+f"(c2), "+f"(c3)
        : "r"(a0), "r"(a1), "r"(a2), "r"(a3), "r"(b0), "r"(b1));
}
__device__ __forceinline__ unsigned long long ffma2(unsigned long long a,
                                                    unsigned long long b,
                                                    unsigned long long c) {
    unsigned long long d;
    asm("fma.rn.f32x2 %0, %1, %2, %3;" : "=l"(d) : "l"(a), "l"(b), "l"(c));
    return d;
}
__device__ __forceinline__ float f2lo(unsigned long long v) { return __uint_as_float((unsigned)v); }
__device__ __forceinline__ float f2hi(unsigned long long v) { return __uint_as_float((unsigned)(v >> 32)); }

// W pattern: (hi, lo, hi) per original k
__device__ __forceinline__ void triple_write(__nv_bfloat16* dst, const float* v) {
    __nv_bfloat16 tmp[24];
#pragma unroll
    for (int j = 0; j < 8; j++) {
        __nv_bfloat16 hi = __float2bfloat16(v[j]);
        __nv_bfloat16 lo = __float2bfloat16(v[j] - __bfloat162float(hi));
        tmp[3 * j] = hi; tmp[3 * j + 1] = lo; tmp[3 * j + 2] = hi;
    }
    uint4* d4 = (uint4*)dst;
    const uint4* s4 = (const uint4*)tmp;
    d4[0] = s4[0]; d4[1] = s4[1]; d4[2] = s4[2];
}
// A pattern: (hi, hi, lo) per original k  — pairs with W's (hi, lo, hi):
//   sum = ah*wh + ah*wl + al*wh
__device__ __forceinline__ void triple_write_A(__nv_bfloat16* dst, const float* v) {
    __nv_bfloat16 tmp[24];
#pragma unroll
    for (int j = 0; j < 8; j++) {
        __nv_bfloat16 hi = __float2bfloat16(v[j]);
        __nv_bfloat16 lo = __float2bfloat16(v[j] - __bfloat162float(hi));
        tmp[3 * j] = hi; tmp[3 * j + 1] = hi; tmp[3 * j + 2] = lo;
    }
    uint4* d4 = (uint4*)dst;
    const uint4* s4 = (const uint4*)tmp;
    d4[0] = s4[0]; d4[1] = s4[1]; d4[2] = s4[2];
}

// ---------------- 0) prep ----------------
__global__ void k_prep(const float* __restrict__ W0, const float* __restrict__ b0,
                       const float* __restrict__ CW, const float* __restrict__ CB,
                       const float* __restrict__ W1, const float* __restrict__ b1,
                       const float* __restrict__ W2,
                       const float4* __restrict__ W3, const float* __restrict__ b3) {
    int i = blockIdx.x * 256 + threadIdx.x;
    int stride = gridDim.x * 256;
    // head Weff
    for (int q = i; q < NHPAD * 64; q += stride) {
        int row = q >> 6, k8 = (q & 63) << 3;
        float v[8];
#pragma unroll
        for (int j = 0; j < 8; j++) {
            int k = k8 + j;
            float w = 0.f;
            if (row < 20000) w = W0[(size_t)row * 512 + k];
            else if (row < NHEAD) w = CW[(size_t)(row - 20000) * 512 + k];
            v[j] = w;
        }
        triple_write(g_Weff + (size_t)row * KPH + 3 * k8, v);
    }
    // W1eff
    for (int q = i; q < N1PAD * 16; q += stride) {
        int row = q >> 4, k8 = (q & 15) << 3;
        float v[8];
#pragma unroll
        for (int j = 0; j < 8; j++)
            v[j] = (row < 20000) ? W1[(size_t)row * 128 + k8 + j] : 0.f;
        triple_write(g_W1eff + (size_t)row * KP1 + 3 * k8, v);
    }
    // W2eff data (96 of 128)
    for (int q = i; q < 160000 * 4; q += stride) {
        int row = q >> 2, k8 = (q & 3) << 3;
        float v[8];
#pragma unroll
        for (int j = 0; j < 8; j++) v[j] = W2[(size_t)row * 32 + k8 + j];
        triple_write(g_W2eff + (size_t)row * KP2 + 3 * k8, v);
    }
    // W2eff zero tail (cols 96..127)
    for (int q = i; q < 160000 * 4; q += stride) {
        int row = q >> 2, part = q & 3;
        ((uint4*)(g_W2eff + (size_t)row * KP2 + 96))[part] = make_uint4(0, 0, 0, 0);
    }
    float4 z = make_float4(0.f, 0.f, 0.f, 0.f);
    float4* W3P = (float4*)g_W3p;
    for (int idx = i; idx < V3PAD * 2; idx += stride)
        W3P[idx] = (idx < 67735 * 2) ? W3[idx] : z;
    for (int idx = i; idx < NHPAD; idx += stride)
        g_headB[idx] = (idx < 20000) ? b0[idx] : (idx < NHEAD ? CB[idx - 20000] : -1e30f);
    for (int idx = i; idx < N1PAD; idx += stride)
        g_b1p[idx] = (idx < 20000) ? b1[idx] : -1e30f;
    for (int idx = i; idx < V3PAD; idx += stride)
        g_b3p[idx] = (idx < 67735) ? b3[idx] : 0.f;
}

// ---------------- 1) projections (8-token tiles) ----------------
__global__ void __launch_bounds__(512)
k_proj(const float* __restrict__ hidden,
       const float* __restrict__ p0, const float* __restrict__ p1,
       const float* __restrict__ p2, const float* __restrict__ p3) {
    __shared__ float h[8][512];
    int t0 = blockIdx.x * 8;
    int tid = threadIdx.x;
    for (int i = tid; i < 8 * 512; i += 512)
        h[i >> 9][i & 511] = hidden[(t0 + (i >> 9)) * 512 + (i & 511)];
    __syncthreads();
    {
        int j = tid;
        float a[8];
#pragma unroll
        for (int i = 0; i < 8; i++) a[i] = 0.f;
#pragma unroll 4
        for (int k = 0; k < 512; k++) {
            float w = p0[k * 512 + j];
#pragma unroll
            for (int i = 0; i < 8; i++) a[i] = fmaf(h[i][k], w, a[i]);
        }
#pragma unroll
        for (int i = 0; i < 8; i++) {
            __nv_bfloat16 hi = __float2bfloat16(a[i]);
            __nv_bfloat16 lo = __float2bfloat16(a[i] - __bfloat162float(hi));
            size_t base = (size_t)(t0 + i) * KPH + 3 * j;
            g_Aeff[base] = hi; g_Aeff[base + 1] = hi; g_Aeff[base + 2] = lo;
        }
    }
    if (tid < 128) {
        int j = tid;
        float a[8];
#pragma unroll
        for (int i = 0; i < 8; i++) a[i] = 0.f;
#pragma unroll 4
        for (int k = 0; k < 512; k++) {
            float w = p1[k * 128 + j];
#pragma unroll
            for (int i = 0; i < 8; i++) a[i] = fmaf(h[i][k], w, a[i]);
        }
#pragma unroll
        for (int i = 0; i < 8; i++) g_hp1[(t0 + i) * 128 + j] = a[i];
    }
    if (tid < 32) {
        int j = tid;
        float a[8];
#pragma unroll
        for (int i = 0; i < 8; i++) a[i] = 0.f;
#pragma unroll 4
        for (int k = 0; k < 512; k++) {
            float w = p2[k * 32 + j];
#pragma unroll
            for (int i = 0; i < 8; i++) a[i] = fmaf(h[i][k], w, a[i]);
        }
#pragma unroll
        for (int i = 0; i < 8; i++) g_hp2[(t0 + i) * 32 + j] = a[i];
    }
    if (tid < 8) {
        int j = tid;
        float a[8];
#pragma unroll
        for (int i = 0; i < 8; i++) a[i] = 0.f;
#pragma unroll 4
        for (int k = 0; k < 512; k++) {
            float w = p3[k * 8 + j];
#pragma unroll
            for (int i = 0; i < 8; i++) a[i] = fmaf(h[i][k], w, a[i]);
        }
#pragma unroll
        for (int i = 0; i < 8; i++) g_hp3[(t0 + i) * 8 + j] = a[i];
    }
}

// ---------------- 2) cluster-id + compaction ----------------
__global__ void k_compact(const int* __restrict__ target) {
    int t = threadIdx.x;
    if (t < 3) g_cnt[t] = 0;
    __syncthreads();
    int tg = target[t];
    int cid = (tg >= 20000) + (tg >= 40000) + (tg >= 200000);
    if (cid > 0) {
        int p = atomicAdd(&g_cnt[cid - 1], 1);
        g_list[cid - 1][p] = t;
        g_pos[t] = p;
    } else {
        g_pos[t] = -1;
    }
}

// ---------------- 2b) gather compacted tokens into A1eff / A2eff -------------
__global__ void k_gather() {
    int i = blockIdx.x * 256 + threadIdx.x;
    int stride = gridDim.x * 256;
    int c1 = g_cnt[0], c2 = g_cnt[1];
    // A1eff: CAP1 slots x 16 k8-groups (E=128)  — A pattern (hi, hi, lo)!
    for (int q = i; q < CAP1 * 16; q += stride) {
        int s = q >> 4, k8 = (q & 15) << 3;
        int sl = (c1 == 0) ? 0 : (s < c1 ? s : c1 - 1);
        int token = g_list[0][sl];
        float v[8];
#pragma unroll
        for (int j = 0; j < 8; j++) v[j] = g_hp1[token * 128 + k8 + j];
        triple_write_A(g_A1eff + (size_t)s * KP1 + 3 * k8, v);
    }
    // A2eff data: CAP2 slots x 4 k8-groups (E=32) — A pattern (hi, hi, lo)!
    for (int q = i; q < CAP2 * 4; q += stride) {
        int s = q >> 2, k8 = (q & 3) << 3;
        int sl = (c2 == 0) ? 0 : (s < c2 ? s : c2 - 1);
        int token = g_list[1][sl];
        float v[8];
#pragma unroll
        for (int j = 0; j < 8; j++) v[j] = g_hp2[token * 32 + k8 + j];
        triple_write_A(g_A2eff + (size_t)s * KP2 + 3 * k8, v);
    }
    // A2eff zero tail
    for (int q = i; q < CAP2 * 4; q += stride) {
        int s = q >> 2, part = q & 3;
        ((uint4*)(g_A2eff + (size_t)s * KP2 + 96))[part] = make_uint4(0, 0, 0, 0);
    }
}

// ---------------- 3) unified MMA GEMM+softmax-partial kernel ------------------
// MODE 0=head, 1=tail1, 2=tail2. 128 tok x 128 rows per CTA, K'=NKC*64.
extern __shared__ __nv_bfloat16 hsm[];
template <int MODE, int NKC, int NCH, int L>
__global__ void __launch_bounds__(256, 2)
k_mma(const int* __restrict__ target, const float* __restrict__ b2) {
    constexpr int KP = NKC * 64;
    const int tile = blockIdx.x, chunk = blockIdx.y;
    int cnt = 0;
    if (MODE) { cnt = g_cnt[MODE - 1]; if (tile * 128 >= cnt) return; }
    const int tid = threadIdx.x, wid = tid >> 5, lane = tid & 31;
    const int t0 = tile * 128, row0 = chunk * 128;
    const int wm = (wid & 1) * 64;
    const int wn = (wid >> 1) * 32;

    __nv_bfloat16* sA = hsm;
    __nv_bfloat16* sB = hsm + 2 * SMHALF;
    const uint32_t sbA = smem_u32(sA);
    const uint32_t sbB = smem_u32(sB);

    const int rowA = wm + ((lane >> 3) & 1) * 8 + (lane & 7);
    const int kA = (lane >> 4) * 8;
    const int rowB = wn + (lane >> 4) * 8 + (lane & 7);
    const int kB = ((lane >> 3) & 1) * 8;

    float acc[4][4][4];
#pragma unroll
    for (int mt = 0; mt < 4; mt++)
#pragma unroll
        for (int nt = 0; nt < 4; nt++)
#pragma unroll
            for (int v = 0; v < 4; v++) acc[mt][nt][v] = 0.f;

    const __nv_bfloat16* gA =
        (MODE == 0 ? g_Aeff : MODE == 1 ? g_A1eff : g_A2eff) + (size_t)t0 * KP;
    const __nv_bfloat16* gB =
        (MODE == 0 ? g_Weff : MODE == 1 ? g_W1eff : g_W2eff) + (size_t)row0 * KP;
    const float* bias = (MODE == 0) ? g_headB : (MODE == 1) ? g_b1p : b2;

#pragma unroll
    for (int j = 0; j < 4; j++) {
        int flat = tid + 256 * j;
        int r = flat >> 3, ku = (flat & 7) * 8;
        *(float4*)(sA + r * PITCH + ku) = *(const float4*)(gA + (size_t)r * KP + ku);
        *(float4*)(sB + r * PITCH + ku) = *(const float4*)(gB + (size_t)r * KP + ku);
    }

    for (int kc = 0; kc < NKC; kc++) {
        __syncthreads();
        int buf = kc & 1;
        if (kc + 1 < NKC) {
            int nb = buf ^ 1;
            const __nv_bfloat16* gA2 = gA + (kc + 1) * 64;
            const __nv_bfloat16* gB2 = gB + (kc + 1) * 64;
#pragma unroll
            for (int j = 0; j < 4; j++) {
                int flat = tid + 256 * j;
                int r = flat >> 3, ku = (flat & 7) * 8;
                *(float4*)(sA + nb * SMHALF + r * PITCH + ku) =
                    *(const float4*)(gA2 + (size_t)r * KP + ku);
                *(float4*)(sB + nb * SMHALF + r * PITCH + ku) =
                    *(const float4*)(gB2 + (size_t)r * KP + ku);
            }
        }
        uint32_t baseA = sbA + buf * (SMHALF * 2);
        uint32_t baseB = sbB + buf * (SMHALF * 2);
#pragma unroll
        for (int ks = 0; ks < 4; ks++) {
            uint32_t a[4][4];
#pragma unroll
            for (int mt = 0; mt < 4; mt++) {
                uint32_t ad = baseA + ((rowA + mt * 16) * PITCH + ks * 16 + kA) * 2;
                ldsm4(a[mt][0], a[mt][1], a[mt][2], a[mt][3], ad);
            }
            uint32_t b[4][2];
#pragma unroll
            for (int p = 0; p < 2; p++) {
                uint32_t bd = baseB + ((rowB + p * 16) * PITCH + ks * 16 + kB) * 2;
                uint32_t r0, r1, r2, r3;
                ldsm4(r0, r1, r2, r3, bd);
                b[2 * p][0] = r0; b[2 * p][1] = r1;
                b[2 * p + 1][0] = r2; b[2 * p + 1][1] = r3;
            }
#pragma unroll
            for (int mt = 0; mt < 4; mt++)
#pragma unroll
                for (int nt = 0; nt < 4; nt++)
                    mma16816(acc[mt][nt][0], acc[mt][nt][1], acc[mt][nt][2], acc[mt][nt][3],
                             a[mt][0], a[mt][1], a[mt][2], a[mt][3],
                             b[nt][0], b[nt][1]);
        }
    }
    __syncthreads();

    float bias_v[4][2];
#pragma unroll
    for (int nt = 0; nt < 4; nt++)
#pragma unroll
        for (int odd = 0; odd < 2; odd++)
            bias_v[nt][odd] = bias[row0 + wn + nt * 8 + ((lane & 3) << 1) + odd];

    float* red = (float*)hsm;
    int colw = ((wid >> 1) << 2) | (lane & 3);
#pragma unroll
    for (int mt = 0; mt < 4; mt++)
#pragma unroll
        for (int half = 0; half < 2; half++) {
            int tokl = wm + mt * 16 + (lane >> 2) + half * 8;
            int nc;
            int token;
            if (MODE == 0) {
                token = t0 + tokl;
                int tg = target[token];
                int cid = (tg >= 20000) + (tg >= 40000) + (tg >= 200000);
                nc = cid ? (NHEAD - cid) : tg;
            } else {
                int slot = t0 + tokl;
                token = g_list[MODE - 1][slot < cnt ? slot : cnt - 1];
                nc = target[token] - L;
            }
            float s = 0.f;
#pragma unroll
            for (int nt = 0; nt < 4; nt++)
#pragma unroll
                for (int odd = 0; odd < 2; odd++) {
                    int row = row0 + wn + nt * 8 + ((lane & 3) << 1) + odd;
                    float lg = acc[mt][nt][half * 2 + odd] + bias_v[nt][odd];
                    s += __expf(lg);
                    if (row == nc) {
                        if (MODE == 0) g_nh[token] = lg;
                        else g_nt[token] = lg;
                    }
                }
            red[tokl * 17 + colw] = s;
        }
    __syncthreads();
    if (tid < 128) {
        float s = 0.f;
#pragma unroll
        for (int c = 0; c < 16; c++) s += red[tid * 17 + c];
        if (MODE == 0)
            g_ph[(size_t)(t0 + tid) * HCHUNKS + chunk] = s;
        else if (MODE == 1)
            g_pt1[(size_t)(t0 + tid) * NCH + chunk] = s;
        else
            g_pt2[(size_t)(t0 + tid) * NCH + chunk] = s;
    }
}

// ---------------- 4) tail3: scalar FFMA2 (E=8) ----------------
__global__ void __launch_bounds__(128, 4)
k_tail3(const int* __restrict__ target) {
    constexpr int E = 8, ROWS = 8, NCH = NCH3;
    constexpr int CROWS = 4 * ROWS;
    constexpr int KP_ = E / 2;
    __shared__ unsigned long long shp[KP_][65];
    __shared__ float red[4][64];
    const float* hp = g_hp3;
    const float* W = g_W3p;
    const float* bias = g_b3p;
    constexpr int V = 67735;
    constexpr int L = 200000;

    int cnt = g_cnt[2];
    int tile = blockIdx.x;
    if (tile * 64 >= cnt) return;
    int chunk = blockIdx.y;
    int tid = threadIdx.x, warp = tid >> 5, lane = tid & 31;
    int row0 = chunk * CROWS + warp * ROWS;

    {
        constexpr int WTOK = 128 / E;
        int tok_sub = tid / E;
        int k = tid % E;
#pragma unroll
        for (int base = 0; base < 64; base += WTOK) {
            int tok = base + tok_sub;
            int slot = tile * 64 + tok;
            int token = g_list[2][slot < cnt ? slot : cnt - 1];
            float v = hp[token * E + k];
            ((float*)&shp[k >> 1][tok])[k & 1] = v;
        }
    }
    __syncthreads();

    unsigned long long acc[ROWS][2];
#pragma unroll
    for (int i = 0; i < ROWS; i++) { acc[i][0] = 0ull; acc[i][1] = 0ull; }
    const float* wp = W + (size_t)row0 * E;
#pragma unroll 2
    for (int k = 0; k < E; k += 4) {
        int kp = k >> 1;
        unsigned long long a0 = shp[kp][lane];
        unsigned long long a1 = shp[kp][lane + 32];
        unsigned long long c0 = shp[kp + 1][lane];
        unsigned long long c1 = shp[kp + 1][lane + 32];
#pragma unroll
        for (int i = 0; i < ROWS; i++) {
            ulonglong2 w = *(const ulonglong2*)(wp + i * E + k);
            acc[i][0] = ffma2(a0, w.x, acc[i][0]);
            acc[i][0] = ffma2(c0, w.y, acc[i][0]);
            acc[i][1] = ffma2(a1, w.x, acc[i][1]);
            acc[i][1] = ffma2(c1, w.y, acc[i][1]);
        }
    }

    int slot0 = tile * 64 + lane, slot1 = slot0 + 32;
    int token0 = g_list[2][slot0 < cnt ? slot0 : cnt - 1];
    int token1 = g_list[2][slot1 < cnt ? slot1 : cnt - 1];
    int rel0 = target[token0] - L;
    int rel1 = target[token1] - L;
    float s0 = 0.f, s1 = 0.f;
#pragma unroll
    for (int i = 0; i < ROWS; i++) {
        int row = row0 + i;
        float bb = bias[row];
        float d0 = f2lo(acc[i][0]) + f2hi(acc[i][0]) + bb;
        float d1 = f2lo(acc[i][1]) + f2hi(acc[i][1]) + bb;
        if (row < V) { s0 += __expf(d0); s1 += __expf(d1); }
        if (row == rel0) g_nt[token0] = d0;
        if (row == rel1) g_nt[token1] = d1;
    }
    red[warp][lane] = s0;
    red[warp][lane + 32] = s1;
    __syncthreads();
    if (warp == 0) {
        float ta = red[0][lane] + red[1][lane] + red[2][lane] + red[3][lane];
        float tb = red[0][lane + 32] + red[1][lane + 32] + red[2][lane + 32] + red[3][lane + 32];
        g_pt3[(size_t)slot0 * NCH + chunk] = ta;
        g_pt3[(size_t)slot1 * NCH + chunk] = tb;
    }
}

// ---------------- 5) combine: warp per token ----------------
__global__ void k_comb(const int* __restrict__ target, float* __restrict__ out) {
    int t = (blockIdx.x * blockDim.x + threadIdx.x) >> 5;
    int lane = threadIdx.x & 31;
    if (t >= NTOK) return;
    float s = 0.f;
    for (int ch = lane; ch < HCHUNKS; ch += 32) s += g_ph[(size_t)t * HCHUNKS + ch];
#pragma unroll
    for (int o = 16; o; o >>= 1) s += __shfl_xor_sync(0xffffffffu, s, o);
    float hl = g_nh[t] - logf(s);
    int tg = target[t];
    int cid = (tg >= 20000) + (tg >= 40000) + (tg >= 200000);
    float nll = -hl;
    if (cid) {
        int p = g_pos[t];
        const float* pt;
        int nch;
        if (cid == 1) { pt = g_pt1 + (size_t)p * NCH1T; nch = NCH1T; }
        else if (cid == 2) { pt = g_pt2 + (size_t)p * NCH2T; nch = NCH2T; }
        else { pt = g_pt3 + (size_t)p * NCH3; nch = NCH3; }
        float st = 0.f;
        for (int ch = lane; ch < nch; ch += 32) st += pt[ch];
#pragma unroll
        for (int o = 16; o; o >>= 1) st += __shfl_xor_sync(0xffffffffu, st, o);
        nll = -(hl + g_nt[t] - logf(st));
    }
    if (lane == 0) out[t] = nll;
}

// ---------------- launch ----------------
extern "C" void kernel_launch(void* const* d_in, const int* in_sizes, int n_in,
                              void* d_out, int out_size) {
    const float* hidden = (const float*)d_in[0];
    const int*   target = (const int*)d_in[1];
    const float* W0 = (const float*)d_in[2];
    const float* b0 = (const float*)d_in[3];
    const float* p0 = (const float*)d_in[4];
    const float* W1 = (const float*)d_in[5];
    const float* b1 = (const float*)d_in[6];
    const float* p1 = (const float*)d_in[7];
    const float* W2 = (const float*)d_in[8];
    const float* b2 = (const float*)d_in[9];
    const float* p2 = (const float*)d_in[10];
    const float* W3 = (const float*)d_in[11];
    const float* b3 = (const float*)d_in[12];
    const float* p3 = (const float*)d_in[13];
    const float* CW = (const float*)d_in[14];
    const float* CB = (const float*)d_in[15];

    cudaFuncSetAttribute(k_mma<0, 24, HCHUNKS, 0>,
                         cudaFuncAttributeMaxDynamicSharedMemorySize, SM_TOT);
    cudaFuncSetAttribute(k_mma<1, 6, NCH1T, 20000>,
                         cudaFuncAttributeMaxDynamicSharedMemorySize, SM_TOT);
    cudaFuncSetAttribute(k_mma<2, 2, NCH2T, 40000>,
                         cudaFuncAttributeMaxDynamicSharedMemorySize, SM_TOT);

    k_prep<<<2048, 256>>>(W0, b0, CW, CB, W1, b1, W2, (const float4*)W3, b3);
    k_proj<<<NTOK / 8, 512>>>(hidden, p0, p1, p2, p3);
    k_compact<<<1, NTOK>>>(target);
    k_gather<<<32, 256>>>();
    k_mma<0, 24, HCHUNKS, 0><<<dim3(8, 157), 256, SM_TOT>>>(target, b2);
    k_mma<2, 2, NCH2T, 40000><<<dim3(6, 1250), 256, SM_TOT>>>(target, b2);
    k_mma<1, 6, NCH1T, 20000><<<dim3(2, 157), 256, SM_TOT>>>(target, b2);
    k_tail3<<<dim3(TILES3, NCH3), 128>>>(target);
    k_comb<<<128, 256>>>(target, (float*)d_out);
}